// round 13
// baseline (speedup 1.0000x reference)
#include <cuda_runtime.h>

#define TLEN 200
#define SP   36
#define BMP  20

#define DUP2(d,s)   asm("mov.b64 %0, {%1,%1};" : "=l"(d) : "f"(s))
#define FMA2(d,a,b) asm("fma.rn.f32x2 %0, %1, %2, %0;" : "+l"(d) : "l"(a), "l"(b))
#define ADD2(d,a)   asm("add.rn.f32x2 %0, %0, %1;" : "+l"(d) : "l"(a))
#define RCPA(d,a)   asm("rcp.approx.f32 %0, %1;" : "=f"(d) : "f"(a))

__device__ __forceinline__ float2 lo2(unsigned long long u) {
    float2 f;
    f.x = __uint_as_float((unsigned)u);
    f.y = __uint_as_float((unsigned)(u >> 32));
    return f;
}

// NN 32x32x32 matmul on 128 threads (warps 0-3):
// thread (ty=tid>>3, tx=tid&7) computes rows (ty, ty+16) x cols 4tx..4tx+3.
__device__ __forceinline__ void mm24(const float* X, const float* Y,
                                     int ty, int tx,
                                     unsigned long long& a01, unsigned long long& a23,
                                     unsigned long long& b01, unsigned long long& b23)
{
    a01 = a23 = b01 = b23 = 0ULL;
    #pragma unroll
    for (int k4 = 0; k4 < 8; ++k4) {
        float4 x0 = *(const float4*)(X + ty*SP + 4*k4);
        float4 x1 = *(const float4*)(X + (ty+16)*SP + 4*k4);
        #pragma unroll
        for (int kk = 0; kk < 4; ++kk) {
            ulonglong2 y2 = *(const ulonglong2*)(Y + (4*k4+kk)*SP + 4*tx);
            float xs0 = (kk==0)?x0.x:(kk==1)?x0.y:(kk==2)?x0.z:x0.w;
            float xs1 = (kk==0)?x1.x:(kk==1)?x1.y:(kk==2)?x1.z:x1.w;
            unsigned long long xd0, xd1;
            DUP2(xd0, xs0);
            DUP2(xd1, xs1);
            FMA2(a01, xd0, y2.x);
            FMA2(a23, xd0, y2.y);
            FMA2(b01, xd1, y2.x);
            FMA2(b23, xd1, y2.y);
        }
    }
}

__device__ __forceinline__ float4 pack2(unsigned long long a, unsigned long long b) {
    float2 u = lo2(a), v = lo2(b);
    float4 o; o.x = u.x; o.y = u.y; o.z = v.x; o.w = v.y;
    return o;
}

__global__ __launch_bounds__(256, 2)
void kf_kernel(const float* __restrict__ Yg, const float* __restrict__ Ug,
               const float* __restrict__ maskg, const float* __restrict__ Ag,
               const float* __restrict__ Bmg, const float* __restrict__ Cg,
               const float* __restrict__ mu0g, const float* __restrict__ Sig0g,
               const float* __restrict__ Qg, const float* __restrict__ Rg,
               float* __restrict__ mf, float* __restrict__ Sf,
               float* __restrict__ mp, float* __restrict__ Sp)
{
    __shared__ __align__(16) float sA [32*SP], sAT[32*SP], sC [32*SP], sCT[32*SP];
    __shared__ __align__(16) float Sig[32*SP], Spr[32*SP], CSb[32*SP], Tm [32*SP], Km [32*SP];
    __shared__ __align__(16) float sBm[32*BMP];
    __shared__ __align__(16) float PR[2][2][68];     // pivot-row pair snapshots, ping-pong
    __shared__ __align__(16) float2 FC2[2][34];      // pivot-col pairs (right warps), ping-pong
    __shared__ __align__(16) float IV[2][4];         // precomputed 2x2 pivot-block inverse
    __shared__ __align__(16) float mu[32], mupr[32], rv[32];
    __shared__ __align__(16) float YV[2][32], UV[2][16];
    __shared__ float MV[2];

    const int tid = threadIdx.x;
    const int b   = blockIdx.x;
    const int mty = (tid & 127) >> 3;   // 0..15: rows (mty, mty+16)
    const int mtx = tid & 7;            // col group (4 cols)
    const int shalf = tid >> 7;         // solve: 0 = left 32 aug cols, 1 = right
    const int scol  = mtx + 8*shalf;    // aug col group 0..15

    const long long btb = (long long)b * TLEN;

    // ---- setup ----
    for (int e = tid; e < 1024; e += 256) {
        int i = e >> 5, j = e & 31;
        float a = Ag[e], c = Cg[e];
        sA [i*SP+j] = a;  sAT[j*SP+i] = a;
        sC [i*SP+j] = c;  sCT[j*SP+i] = c;
        Sig[i*SP+j] = Sig0g[e];
    }
    for (int e = tid; e < 512; e += 256) sBm[(e>>4)*BMP + (e&15)] = Bmg[e];
    if (tid < 32) { mu[tid] = mu0g[tid]; YV[0][tid] = Yg[btb*32 + tid]; }
    else if (tid < 48) UV[0][tid-32] = Ug[btb*16 + (tid-32)];
    else if (tid == 48) MV[0] = maskg[btb];

    // hoisted constants for warps 0-3: Q rows (P2) and R rows (solve seed)
    ulonglong2 qh0 = make_ulonglong2(0,0), qh1 = make_ulonglong2(0,0);
    float4 rh0 = {0,0,0,0}, rh1 = {0,0,0,0};
    if (tid < 128) {
        qh0 = __ldg((const ulonglong2*)(Qg + mty*32 + 4*mtx));
        qh1 = __ldg((const ulonglong2*)(Qg + (mty+16)*32 + 4*mtx));
        rh0 = __ldg((const float4*)(Rg + mty*32 + 4*mtx));
        rh1 = __ldg((const float4*)(Rg + (mty+16)*32 + 4*mtx));
    }
    __syncthreads();

    for (int t = 0; t < TLEN; ++t) {
        const long long bt = btb + t;
        const int cur = t & 1, nxtb = cur ^ 1;

        // ---- P1: Tm = A*Sig (w0-3); stage t+1 inputs (w4-5) ----
        if (tid < 128) {
            unsigned long long a01,a23,b01,b23;
            mm24(sA, Sig, mty, mtx, a01,a23,b01,b23);
            *(float4*)(Tm + mty*SP + 4*mtx)      = pack2(a01,a23);
            *(float4*)(Tm + (mty+16)*SP + 4*mtx) = pack2(b01,b23);
        } else if (t + 1 < TLEN) {
            if (tid < 160)       YV[nxtb][tid-128] = Yg[(bt+1)*32 + (tid-128)];
            else if (tid < 176)  UV[nxtb][tid-160] = Ug[(bt+1)*16 + (tid-160)];
            else if (tid == 176) MV[nxtb] = maskg[bt+1];
        }
        __syncthreads();

        // ---- P2: Spr = Tm*A^T + Q (w0-3); mu_pred (w7, +mp) ----
        if (tid < 128) {
            unsigned long long a01,a23,b01,b23;
            mm24(Tm, sAT, mty, mtx, a01,a23,b01,b23);
            ADD2(a01, qh0.x); ADD2(a23, qh0.y);
            ADD2(b01, qh1.x); ADD2(b23, qh1.y);
            *(float4*)(Spr + mty*SP + 4*mtx)      = pack2(a01,a23);
            *(float4*)(Spr + (mty+16)*SP + 4*mtx) = pack2(b01,b23);
        } else if (tid >= 224) {
            int l = tid - 224;
            float acc = 0.f;
            #pragma unroll
            for (int c = 0; c < 8; ++c) {
                float4 a = *(const float4*)(sA + l*SP + 4*c);
                float4 m = *(const float4*)(mu + 4*c);
                acc += a.x*m.x + a.y*m.y + a.z*m.z + a.w*m.w;
            }
            #pragma unroll
            for (int c = 0; c < 4; ++c) {
                float4 a = *(const float4*)(sBm + l*BMP + 4*c);
                float4 m = *(const float4*)(UV[cur] + 4*c);
                acc += a.x*m.x + a.y*m.y + a.z*m.z + a.w*m.w;
            }
            mupr[l] = acc;
            mp[bt*32 + l] = acc;
        }
        __syncthreads();

        // ---- P3: CSb = C*Spr (w0-3); rv (w7); Sp store (w4-6) ----
        if (tid < 128) {
            unsigned long long a01,a23,b01,b23;
            mm24(sC, Spr, mty, mtx, a01,a23,b01,b23);
            *(float4*)(CSb + mty*SP + 4*mtx)      = pack2(a01,a23);
            *(float4*)(CSb + (mty+16)*SP + 4*mtx) = pack2(b01,b23);
        } else if (tid >= 224) {
            int l = tid - 224;
            float acc = YV[cur][l];
            #pragma unroll
            for (int c = 0; c < 8; ++c) {
                float4 a = *(const float4*)(sC + l*SP + 4*c);
                float4 m = *(const float4*)(mupr + 4*c);
                acc -= a.x*m.x + a.y*m.y + a.z*m.z + a.w*m.w;
            }
            rv[l] = acc;
        } else {
            // warps 4-6: Sp[bt] = Spr (256 float4 slots over 96 threads)
            for (int f = tid - 128; f < 256; f += 96) {
                int row = f >> 3, c4 = f & 7;
                float4 v = *(const float4*)(Spr + row*SP + 4*c4);
                *(float4*)(Sp + bt*1024 + f*4) = v;
            }
        }
        __syncthreads();

        // ================== solve (all 256 threads, 2 rows x 4 cols each) ==================
        float4 e0, e1;
        if (shalf == 0) {
            // fused: S = CS*C^T + R directly into solve registers (warps 0-3)
            unsigned long long a01,a23,b01,b23;
            mm24(CSb, sCT, mty, mtx, a01,a23,b01,b23);
            e0 = pack2(a01,a23);
            e1 = pack2(b01,b23);
            e0.x += rh0.x; e0.y += rh0.y; e0.z += rh0.z; e0.w += rh0.w;
            e1.x += rh1.x; e1.y += rh1.y; e1.z += rh1.z; e1.w += rh1.w;
        } else {
            // right half: load CS slices (warps 4-7)
            e0 = *(const float4*)(CSb + mty*SP + 4*mtx);
            e1 = *(const float4*)(CSb + (mty+16)*SP + 4*mtx);
        }
        // seed snapshots for pivot pair (0,1)
        if (mty == 0) *(float4*)(&PR[0][0][4*scol]) = e0;
        if (mty == 1) *(float4*)(&PR[0][1][4*scol]) = e0;
        if (shalf == 0 && mtx == 0) {
            FC2[0][mty]      = make_float2(e0.x, e0.y);
            FC2[0][mty + 16] = make_float2(e1.x, e1.y);
        }
        // seed IV[0]: inverse of aug[0:2][0:2]; holders: (mty=0,mtx=0) and (mty=1,mtx=0)
        if (shalf == 0) {
            float m0 = e0.x, m1 = e0.y;
            float o0 = __shfl_xor_sync(0xffffffffu, m0, 8);
            float o1 = __shfl_xor_sync(0xffffffffu, m1, 8);
            if (mtx == 0 && mty < 2) {
                bool isT0 = (mty == 0);
                float a  = isT0 ? m0 : o0, bb = isT0 ? m1 : o1;
                float c  = isT0 ? o0 : m0, d  = isT0 ? o1 : m1;
                float det = a*d - bb*c, dinv;
                RCPA(dinv, det);
                float2 st = isT0 ? make_float2(d*dinv, -bb*dinv)
                                 : make_float2(-c*dinv, a*dinv);
                *(float2*)&IV[0][isT0 ? 0 : 2] = st;
            }
        }
        __syncthreads();

        // 16 paired-pivot Gauss-Jordan rounds (pivot-block inverse precomputed in IV)
        #pragma unroll
        for (int rr = 0; rr < 16; ++rr) {
            const int rb = rr & 1, nb = rb ^ 1;
            const int p0 = 2*rr, p1 = 2*rr + 1;
            const int cqc = p0 >> 2, c0c = p0 & 3;         // current pivot colgroup/comp
            // g values: left warps via in-warp shuffle, right warps via FC2
            float g00, g01, g10, g11;
            if (shalf == 0) {
                int srcLane = 8*(mty & 3) + cqc;
                float cA0 = (c0c == 0) ? e0.x : e0.z, cA1 = (c0c == 0) ? e0.y : e0.w;
                float cB0 = (c0c == 0) ? e1.x : e1.z, cB1 = (c0c == 0) ? e1.y : e1.w;
                g00 = __shfl_sync(0xffffffffu, cA0, srcLane);
                g01 = __shfl_sync(0xffffffffu, cA1, srcLane);
                g10 = __shfl_sync(0xffffffffu, cB0, srcLane);
                g11 = __shfl_sync(0xffffffffu, cB1, srcLane);
            } else {
                float2 f0 = FC2[rb][mty];
                float2 f1 = FC2[rb][mty + 16];
                g00 = f0.x; g01 = f0.y; g10 = f1.x; g11 = f1.y;
            }
            g00 -= (mty      == p0) ? 1.f : 0.f;
            g01 -= (mty      == p1) ? 1.f : 0.f;
            g10 -= (mty + 16 == p0) ? 1.f : 0.f;
            g11 -= (mty + 16 == p1) ? 1.f : 0.f;

            float4 P0 = *(const float4*)(&PR[rb][0][4*scol]);
            float4 P1 = *(const float4*)(&PR[rb][1][4*scol]);
            float4 iv = *(const float4*)IV[rb];            // (i00,i01,i10,i11)
            float4 W0, W1;
            W0.x = iv.x*P0.x + iv.y*P1.x;  W0.y = iv.x*P0.y + iv.y*P1.y;
            W0.z = iv.x*P0.z + iv.y*P1.z;  W0.w = iv.x*P0.w + iv.y*P1.w;
            W1.x = iv.z*P0.x + iv.w*P1.x;  W1.y = iv.z*P0.y + iv.w*P1.y;
            W1.z = iv.z*P0.z + iv.w*P1.z;  W1.w = iv.z*P0.w + iv.w*P1.w;

            e0.x -= g00*W0.x + g01*W1.x;  e0.y -= g00*W0.y + g01*W1.y;
            e0.z -= g00*W0.z + g01*W1.z;  e0.w -= g00*W0.w + g01*W1.w;
            e1.x -= g10*W0.x + g11*W1.x;  e1.y -= g10*W0.y + g11*W1.y;
            e1.z -= g10*W0.z + g11*W1.z;  e1.w -= g10*W0.w + g11*W1.w;

            if (rr < 15) {
                const int q0 = p0 + 2, q1 = p0 + 3;
                if (mty      == q0) *(float4*)(&PR[nb][0][4*scol]) = e0;
                if (mty + 16 == q0) *(float4*)(&PR[nb][0][4*scol]) = e1;
                if (mty      == q1) *(float4*)(&PR[nb][1][4*scol]) = e0;
                if (mty + 16 == q1) *(float4*)(&PR[nb][1][4*scol]) = e1;
                const int cqn = q0 >> 2, c0n = q0 & 3;     // next pivot colgroup/comp
                if (shalf == 0 && mtx == cqn) {
                    FC2[nb][mty]      = (c0n == 0) ? make_float2(e0.x, e0.y)
                                                   : make_float2(e0.z, e0.w);
                    FC2[nb][mty + 16] = (c0n == 0) ? make_float2(e1.x, e1.y)
                                                   : make_float2(e1.z, e1.w);
                }
                // precompute next round's 2x2 pivot-block inverse (left warps)
                if (shalf == 0) {
                    const bool hin = (q0 >= 16);
                    const int  m0r = q0 & 15;              // holder row (lower)
                    float4 srcv = hin ? e1 : e0;
                    float m0 = (c0n == 0) ? srcv.x : srcv.z;
                    float m1 = (c0n == 0) ? srcv.y : srcv.w;
                    float o0 = __shfl_xor_sync(0xffffffffu, m0, 8);
                    float o1 = __shfl_xor_sync(0xffffffffu, m1, 8);
                    if (mtx == cqn && (mty == m0r || mty == m0r + 1)) {
                        bool isT0 = (mty == m0r);
                        float a  = isT0 ? m0 : o0, bb = isT0 ? m1 : o1;
                        float c  = isT0 ? o0 : m0, d  = isT0 ? o1 : m1;
                        float det = a*d - bb*c, dinv;
                        RCPA(dinv, det);
                        float2 st = isT0 ? make_float2(d*dinv, -bb*dinv)
                                         : make_float2(-c*dinv, a*dinv);
                        *(float2*)&IV[nb][isT0 ? 0 : 2] = st;
                    }
                }
            } else if (shalf == 1) {
                // K = mval * X^T into Km
                const float mv = MV[cur];
                const int a0 = 4*mtx;
                Km[(a0+0)*SP + mty]      = mv*e0.x;
                Km[(a0+1)*SP + mty]      = mv*e0.y;
                Km[(a0+2)*SP + mty]      = mv*e0.z;
                Km[(a0+3)*SP + mty]      = mv*e0.w;
                Km[(a0+0)*SP + mty+16]   = mv*e1.x;
                Km[(a0+1)*SP + mty+16]   = mv*e1.y;
                Km[(a0+2)*SP + mty+16]   = mv*e1.z;
                Km[(a0+3)*SP + mty+16]   = mv*e1.w;
            }
            __syncthreads();
        }

        // ---- P8: Sig = Spr - Km*CSb (w0-3, +Sf); mu_new (w7, +mf) ----
        if (tid < 128) {
            unsigned long long a01,a23,b01,b23;
            mm24(Km, CSb, mty, mtx, a01,a23,b01,b23);
            float4 a0 = pack2(a01,a23);
            float4 a1 = pack2(b01,b23);
            float4 s0 = *(const float4*)(Spr + mty*SP + 4*mtx);
            float4 s1 = *(const float4*)(Spr + (mty+16)*SP + 4*mtx);
            float4 o0 = { s0.x - a0.x, s0.y - a0.y, s0.z - a0.z, s0.w - a0.w };
            float4 o1 = { s1.x - a1.x, s1.y - a1.y, s1.z - a1.z, s1.w - a1.w };
            *(float4*)(Sig + mty*SP + 4*mtx)      = o0;
            *(float4*)(Sig + (mty+16)*SP + 4*mtx) = o1;
            *(float4*)(Sf + bt*1024 + mty*32 + 4*mtx)      = o0;
            *(float4*)(Sf + bt*1024 + (mty+16)*32 + 4*mtx) = o1;
        } else if (tid >= 224) {
            int l = tid - 224;
            float acc = 0.f;
            #pragma unroll
            for (int c = 0; c < 8; ++c) {
                float4 a = *(const float4*)(Km + l*SP + 4*c);
                float4 m = *(const float4*)(rv + 4*c);
                acc += a.x*m.x + a.y*m.y + a.z*m.z + a.w*m.w;
            }
            float mun = mupr[l] + acc;
            mu[l] = mun;
            mf[bt*32 + l] = mun;
        }
        __syncthreads();
    }
}

extern "C" void kernel_launch(void* const* d_in, const int* in_sizes, int n_in,
                              void* d_out, int out_size)
{
    const float* Y    = (const float*)d_in[0];
    const float* U    = (const float*)d_in[1];
    const float* mask = (const float*)d_in[2];
    const float* A    = (const float*)d_in[3];
    const float* Bm   = (const float*)d_in[4];
    const float* C    = (const float*)d_in[5];
    const float* mu0  = (const float*)d_in[6];
    const float* Sig0 = (const float*)d_in[7];
    const float* Q    = (const float*)d_in[8];
    const float* R    = (const float*)d_in[9];

    const int BT = in_sizes[2];
    const int B  = BT / TLEN;

    float* out = (float*)d_out;
    float* mf = out;
    float* Sf = mf + (long long)BT * 32;
    float* mp = Sf + (long long)BT * 1024;
    float* Sp = mp + (long long)BT * 32;

    kf_kernel<<<B, 256>>>(Y, U, mask, A, Bm, C, mu0, Sig0, Q, R, mf, Sf, mp, Sp);
}

// round 14
// speedup vs baseline: 1.2622x; 1.2622x over previous
#include <cuda_runtime.h>

#define TLEN 200
#define SP   36
#define BMP  20

// dynamic smem offsets (floats)
#define O_SA   0
#define O_SAT  1152
#define O_SC   2304
#define O_SCT  3456
#define O_SG   4608
#define O_SGT  5760
#define O_SCQ  6912
#define O_SSR  8064
#define O_SIG  9216
#define O_SPR  10368
#define O_CSB  11520
#define O_TM   12672
#define O_KM   13824
#define O_SBM  14976   // 640
#define O_PR   15616   // [2][2][68] = 272
#define O_FC2  15888   // [2][34] float2 = 136 floats
#define O_MU   16032
#define O_MUPR 16064
#define O_RV   16096
#define O_YV   16128   // [2][32]
#define O_UV   16192   // [2][16]
#define O_MV   16224   // [2]
#define SMEM_FLOATS 16232
#define SMEM_BYTES  (SMEM_FLOATS*4)

#define DUP2(d,s)   asm("mov.b64 %0, {%1,%1};" : "=l"(d) : "f"(s))
#define FMA2(d,a,b) asm("fma.rn.f32x2 %0, %1, %2, %0;" : "+l"(d) : "l"(a), "l"(b))
#define ADD2(d,a)   asm("add.rn.f32x2 %0, %0, %1;" : "+l"(d) : "l"(a))
#define RCPA(d,a)   asm("rcp.approx.f32 %0, %1;" : "=f"(d) : "f"(a))

__device__ __forceinline__ float2 lo2(unsigned long long u) {
    float2 f;
    f.x = __uint_as_float((unsigned)u);
    f.y = __uint_as_float((unsigned)(u >> 32));
    return f;
}

__device__ __forceinline__ float4 pack2(unsigned long long a, unsigned long long b) {
    float2 u = lo2(a), v = lo2(b);
    float4 o; o.x = u.x; o.y = u.y; o.z = v.x; o.w = v.y;
    return o;
}

// 2x4-tile NN matmul fragment (128 threads, warps 0-3): rows (ty, ty+16) x cols 4tx..
__device__ __forceinline__ void mm24(const float* X, const float* Y,
                                     int ty, int tx,
                                     unsigned long long& a01, unsigned long long& a23,
                                     unsigned long long& b01, unsigned long long& b23)
{
    a01 = a23 = b01 = b23 = 0ULL;
    #pragma unroll
    for (int k4 = 0; k4 < 8; ++k4) {
        float4 x0 = *(const float4*)(X + ty*SP + 4*k4);
        float4 x1 = *(const float4*)(X + (ty+16)*SP + 4*k4);
        #pragma unroll
        for (int kk = 0; kk < 4; ++kk) {
            ulonglong2 y2 = *(const ulonglong2*)(Y + (4*k4+kk)*SP + 4*tx);
            float xs0 = (kk==0)?x0.x:(kk==1)?x0.y:(kk==2)?x0.z:x0.w;
            float xs1 = (kk==0)?x1.x:(kk==1)?x1.y:(kk==2)?x1.z:x1.w;
            unsigned long long xd0, xd1;
            DUP2(xd0, xs0);
            DUP2(xd1, xs1);
            FMA2(a01, xd0, y2.x);
            FMA2(a23, xd0, y2.y);
            FMA2(b01, xd1, y2.x);
            FMA2(b23, xd1, y2.y);
        }
    }
}

// 4x4-tile NN matmul fragment (64 threads): rows 4rg..4rg+3 x cols 4cg..4cg+3.
__device__ __forceinline__ void mm44(const float* X, const float* Y, int rg, int cg,
                                     unsigned long long acc[4][2])
{
    #pragma unroll
    for (int r = 0; r < 4; ++r) { acc[r][0] = 0ULL; acc[r][1] = 0ULL; }
    #pragma unroll
    for (int k4 = 0; k4 < 8; ++k4) {
        float4 x0 = *(const float4*)(X + (4*rg+0)*SP + 4*k4);
        float4 x1 = *(const float4*)(X + (4*rg+1)*SP + 4*k4);
        float4 x2 = *(const float4*)(X + (4*rg+2)*SP + 4*k4);
        float4 x3 = *(const float4*)(X + (4*rg+3)*SP + 4*k4);
        #pragma unroll
        for (int kk = 0; kk < 4; ++kk) {
            ulonglong2 y2 = *(const ulonglong2*)(Y + (4*k4+kk)*SP + 4*cg);
            float s0 = (kk==0)?x0.x:(kk==1)?x0.y:(kk==2)?x0.z:x0.w;
            float s1 = (kk==0)?x1.x:(kk==1)?x1.y:(kk==2)?x1.z:x1.w;
            float s2 = (kk==0)?x2.x:(kk==1)?x2.y:(kk==2)?x2.z:x2.w;
            float s3 = (kk==0)?x3.x:(kk==1)?x3.y:(kk==2)?x3.z:x3.w;
            unsigned long long d0,d1,d2,d3;
            DUP2(d0,s0); DUP2(d1,s1); DUP2(d2,s2); DUP2(d3,s3);
            FMA2(acc[0][0],d0,y2.x); FMA2(acc[0][1],d0,y2.y);
            FMA2(acc[1][0],d1,y2.x); FMA2(acc[1][1],d1,y2.y);
            FMA2(acc[2][0],d2,y2.x); FMA2(acc[2][1],d2,y2.y);
            FMA2(acc[3][0],d3,y2.x); FMA2(acc[3][1],d3,y2.y);
        }
    }
}

__global__ __launch_bounds__(256, 2)
void kf_kernel(const float* __restrict__ Yg, const float* __restrict__ Ug,
               const float* __restrict__ maskg, const float* __restrict__ Ag,
               const float* __restrict__ Bmg, const float* __restrict__ Cg,
               const float* __restrict__ mu0g, const float* __restrict__ Sig0g,
               const float* __restrict__ Qg, const float* __restrict__ Rg,
               float* __restrict__ mf, float* __restrict__ Sf,
               float* __restrict__ mp, float* __restrict__ Sp)
{
    extern __shared__ float dyn[];
    float* sA  = dyn + O_SA;
    float* sAT = dyn + O_SAT;
    float* sC  = dyn + O_SC;
    float* sCT = dyn + O_SCT;
    float* sG  = dyn + O_SG;
    float* sGT = dyn + O_SGT;
    float* sCQ = dyn + O_SCQ;
    float* sSR = dyn + O_SSR;
    float* Sig = dyn + O_SIG;
    float* Spr = dyn + O_SPR;
    float* CSb = dyn + O_CSB;
    float* Tm  = dyn + O_TM;
    float* Km  = dyn + O_KM;
    float* sBm = dyn + O_SBM;
    float* PRb = dyn + O_PR;           // PR[rb][row01][68] -> PRb + (rb*2+row)*68
    float2* FC2b = (float2*)(dyn + O_FC2);  // FC2[rb][34]  -> FC2b + rb*34
    float* mu   = dyn + O_MU;
    float* mupr = dyn + O_MUPR;
    float* rv   = dyn + O_RV;
    float* YV   = dyn + O_YV;          // [2][32]
    float* UV   = dyn + O_UV;          // [2][16]
    float* MV   = dyn + O_MV;

    const int tid = threadIdx.x;
    const int b   = blockIdx.x;
    const int mty = (tid & 127) >> 3;   // solve/mm24: rows (mty, mty+16)
    const int mtx = tid & 7;            // col group
    const int shalf = tid >> 7;
    const int scol  = mtx + 8*shalf;
    const int idx4  = tid & 63;         // mm44 coords
    const int rg    = idx4 >> 3;
    const int cg    = idx4 & 7;

    const long long btb = (long long)b * TLEN;

    // ---- pre-a: constants, initial state, t=0 inputs ----
    for (int e = tid; e < 1024; e += 256) {
        int i = e >> 5, j = e & 31;
        float a = Ag[e], c = Cg[e];
        sA [i*SP+j] = a;  sAT[j*SP+i] = a;
        sC [i*SP+j] = c;  sCT[j*SP+i] = c;
        Sig[i*SP+j] = Sig0g[e];
        Tm [i*SP+j] = Qg[e];            // Tm temporarily holds Q
    }
    for (int e = tid; e < 512; e += 256) sBm[(e>>4)*BMP + (e&15)] = Bmg[e];
    if (tid < 32) { mu[tid] = mu0g[tid]; YV[tid] = Yg[btb*32 + tid]; }
    else if (tid < 48) UV[tid-32] = Ug[btb*16 + (tid-32)];
    else if (tid == 48) MV[0] = maskg[btb];
    __syncthreads();

    // ---- pre-b: G = C*A (-> sG, sGT), CQ = C*Q (-> sCQ)  [w0-3, mm24] ----
    if (tid < 128) {
        unsigned long long a01,a23,b01,b23;
        mm24(sC, sA, mty, mtx, a01,a23,b01,b23);
        *(float4*)(sG + mty*SP + 4*mtx)      = pack2(a01,a23);
        *(float4*)(sG + (mty+16)*SP + 4*mtx) = pack2(b01,b23);
        float2 A01=lo2(a01),A23=lo2(a23),B01f=lo2(b01),B23f=lo2(b23);
        sGT[(4*mtx+0)*SP + mty] = A01.x;  sGT[(4*mtx+1)*SP + mty] = A01.y;
        sGT[(4*mtx+2)*SP + mty] = A23.x;  sGT[(4*mtx+3)*SP + mty] = A23.y;
        sGT[(4*mtx+0)*SP + mty+16] = B01f.x;  sGT[(4*mtx+1)*SP + mty+16] = B01f.y;
        sGT[(4*mtx+2)*SP + mty+16] = B23f.x;  sGT[(4*mtx+3)*SP + mty+16] = B23f.y;
        mm24(sC, Tm, mty, mtx, a01,a23,b01,b23);
        *(float4*)(sCQ + mty*SP + 4*mtx)      = pack2(a01,a23);
        *(float4*)(sCQ + (mty+16)*SP + 4*mtx) = pack2(b01,b23);
    }
    __syncthreads();

    // ---- pre-c: SR0 = CQ*C^T + R -> sSR  [w0-3, mm24] ----
    if (tid < 128) {
        unsigned long long a01,a23,b01,b23;
        mm24(sCQ, sCT, mty, mtx, a01,a23,b01,b23);
        ulonglong2 r0 = __ldg((const ulonglong2*)(Rg + mty*32 + 4*mtx));
        ulonglong2 r1 = __ldg((const ulonglong2*)(Rg + (mty+16)*32 + 4*mtx));
        ADD2(a01, r0.x); ADD2(a23, r0.y); ADD2(b01, r1.x); ADD2(b23, r1.y);
        *(float4*)(sSR + mty*SP + 4*mtx)      = pack2(a01,a23);
        *(float4*)(sSR + (mty+16)*SP + 4*mtx) = pack2(b01,b23);
    }
    __syncthreads();

    // hoisted per-thread constants
    float4 sr0 = {0,0,0,0}, sr1 = {0,0,0,0};    // SR0 rows (solve seed, w0-3)
    if (tid < 128) {
        sr0 = *(const float4*)(sSR + mty*SP + 4*mtx);
        sr1 = *(const float4*)(sSR + (mty+16)*SP + 4*mtx);
    }
    ulonglong2 qh[4];                           // Q rows for mm44 coords (w0-1)
    if (tid < 64) {
        #pragma unroll
        for (int r = 0; r < 4; ++r)
            qh[r] = __ldg((const ulonglong2*)(Qg + (4*rg+r)*32 + 4*cg));
    }

    for (int t = 0; t < TLEN; ++t) {
        const long long bt = btb + t;
        const int cur = t & 1, nxtb = cur ^ 1;

        // ---- P1: T1 = A*Sig (w0-1, mm44) || T2 = G*Sig (w2-3, mm44) || stage t+1 (w4-5) ----
        if (tid < 64) {
            unsigned long long acc[4][2];
            mm44(sA, Sig, rg, cg, acc);
            #pragma unroll
            for (int r = 0; r < 4; ++r)
                *(float4*)(Tm + (4*rg+r)*SP + 4*cg) = pack2(acc[r][0], acc[r][1]);
        } else if (tid < 128) {
            unsigned long long acc[4][2];
            mm44(sG, Sig, rg, cg, acc);
            #pragma unroll
            for (int r = 0; r < 4; ++r)
                *(float4*)(Km + (4*rg+r)*SP + 4*cg) = pack2(acc[r][0], acc[r][1]);
        } else if (t + 1 < TLEN) {
            if (tid < 160)       YV[nxtb*32 + (tid-128)] = Yg[(bt+1)*32 + (tid-128)];
            else if (tid < 176)  UV[nxtb*16 + (tid-160)] = Ug[(bt+1)*16 + (tid-160)];
            else if (tid == 176) MV[nxtb] = maskg[bt+1];
        }
        __syncthreads();

        // ---- P2: Spr = T1*A^T + Q (w0-1) || CSb = T2*A^T + CQ (w2-3) || mu_pred (w7) ----
        if (tid < 64) {
            unsigned long long acc[4][2];
            mm44(Tm, sAT, rg, cg, acc);
            #pragma unroll
            for (int r = 0; r < 4; ++r) {
                ADD2(acc[r][0], qh[r].x);
                ADD2(acc[r][1], qh[r].y);
                *(float4*)(Spr + (4*rg+r)*SP + 4*cg) = pack2(acc[r][0], acc[r][1]);
            }
        } else if (tid < 128) {
            unsigned long long acc[4][2];
            mm44(Km, sAT, rg, cg, acc);
            #pragma unroll
            for (int r = 0; r < 4; ++r) {
                ulonglong2 cq = *(const ulonglong2*)(sCQ + (4*rg+r)*SP + 4*cg);
                ADD2(acc[r][0], cq.x);
                ADD2(acc[r][1], cq.y);
                *(float4*)(CSb + (4*rg+r)*SP + 4*cg) = pack2(acc[r][0], acc[r][1]);
            }
        } else if (tid >= 224) {
            int l = tid - 224;
            float acc = 0.f;
            #pragma unroll
            for (int c = 0; c < 8; ++c) {
                float4 a = *(const float4*)(sA + l*SP + 4*c);
                float4 m = *(const float4*)(mu + 4*c);
                acc += a.x*m.x + a.y*m.y + a.z*m.z + a.w*m.w;
            }
            #pragma unroll
            for (int c = 0; c < 4; ++c) {
                float4 a = *(const float4*)(sBm + l*BMP + 4*c);
                float4 m = *(const float4*)(UV + cur*16 + 4*c);
                acc += a.x*m.x + a.y*m.y + a.z*m.z + a.w*m.w;
            }
            mupr[l] = acc;
            mp[bt*32 + l] = acc;
        }
        __syncthreads();

        // ---- P3/seed: S = T2*G^T + SR0 fused into solve regs (w0-3);
        //               CS slices (w4-7); Sp store (w4-6); rv (w7) ----
        float4 e0, e1;
        if (shalf == 0) {
            unsigned long long a01,a23,b01,b23;
            mm24(Km, sGT, mty, mtx, a01,a23,b01,b23);   // Km still holds T2
            e0 = pack2(a01,a23);
            e1 = pack2(b01,b23);
            e0.x += sr0.x; e0.y += sr0.y; e0.z += sr0.z; e0.w += sr0.w;
            e1.x += sr1.x; e1.y += sr1.y; e1.z += sr1.z; e1.w += sr1.w;
        } else {
            e0 = *(const float4*)(CSb + mty*SP + 4*mtx);
            e1 = *(const float4*)(CSb + (mty+16)*SP + 4*mtx);
            if (tid < 224) {
                // warps 4-6: Sp[bt] = Spr
                for (int f = tid - 128; f < 256; f += 96) {
                    int row = f >> 3, c4 = f & 7;
                    float4 v = *(const float4*)(Spr + row*SP + 4*c4);
                    *(float4*)(Sp + bt*1024 + f*4) = v;
                }
            } else {
                int l = tid - 224;
                float acc = YV[cur*32 + l];
                #pragma unroll
                for (int c = 0; c < 8; ++c) {
                    float4 a = *(const float4*)(sC + l*SP + 4*c);
                    float4 m = *(const float4*)(mupr + 4*c);
                    acc -= a.x*m.x + a.y*m.y + a.z*m.z + a.w*m.w;
                }
                rv[l] = acc;
            }
        }
        // seed snapshots for pivot pair (0,1)
        if (mty == 0) *(float4*)(PRb + 0*68 + 4*scol) = e0;
        if (mty == 1) *(float4*)(PRb + 1*68 + 4*scol) = e0;
        if (shalf == 0 && mtx == 0) {
            FC2b[mty]      = make_float2(e0.x, e0.y);
            FC2b[mty + 16] = make_float2(e1.x, e1.y);
        }
        __syncthreads();

        // ---- 16 paired-pivot Gauss-Jordan rounds (R11-exact) ----
        #pragma unroll
        for (int rr = 0; rr < 16; ++rr) {
            const int rb = rr & 1, nb = rb ^ 1;
            const int p0 = 2*rr, p1 = 2*rr + 1;
            const float* PR0 = PRb + (rb*2)*68;
            const float* PR1 = PR0 + 68;
            const float2* FCc = FC2b + rb*34;
            float4 P0 = *(const float4*)(PR0 + 4*scol);
            float4 P1 = *(const float4*)(PR1 + 4*scol);
            float B00 = PR0[p0], B01v = PR0[p1];
            float B10 = PR1[p0], B11v = PR1[p1];
            float det = B00*B11v - B01v*B10;
            float dinv;
            RCPA(dinv, det);
            float i00 =  B11v*dinv, i01 = -B01v*dinv;
            float i10 = -B10 *dinv, i11 =  B00 *dinv;
            float4 W0, W1;
            W0.x = i00*P0.x + i01*P1.x;  W0.y = i00*P0.y + i01*P1.y;
            W0.z = i00*P0.z + i01*P1.z;  W0.w = i00*P0.w + i01*P1.w;
            W1.x = i10*P0.x + i11*P1.x;  W1.y = i10*P0.y + i11*P1.y;
            W1.z = i10*P0.z + i11*P1.z;  W1.w = i10*P0.w + i11*P1.w;
            float2 f0 = FCc[mty];
            float2 f1 = FCc[mty + 16];
            float g00 = f0.x - ((mty      == p0) ? 1.f : 0.f);
            float g01 = f0.y - ((mty      == p1) ? 1.f : 0.f);
            float g10 = f1.x - ((mty + 16 == p0) ? 1.f : 0.f);
            float g11 = f1.y - ((mty + 16 == p1) ? 1.f : 0.f);
            e0.x -= g00*W0.x + g01*W1.x;  e0.y -= g00*W0.y + g01*W1.y;
            e0.z -= g00*W0.z + g01*W1.z;  e0.w -= g00*W0.w + g01*W1.w;
            e1.x -= g10*W0.x + g11*W1.x;  e1.y -= g10*W0.y + g11*W1.y;
            e1.z -= g10*W0.z + g11*W1.z;  e1.w -= g10*W0.w + g11*W1.w;
            if (rr < 15) {
                const int q0 = p0 + 2, q1 = p0 + 3;
                float* PN0 = PRb + (nb*2)*68;
                float* PN1 = PN0 + 68;
                if (mty      == q0) *(float4*)(PN0 + 4*scol) = e0;
                if (mty + 16 == q0) *(float4*)(PN0 + 4*scol) = e1;
                if (mty      == q1) *(float4*)(PN1 + 4*scol) = e0;
                if (mty + 16 == q1) *(float4*)(PN1 + 4*scol) = e1;
                const int cq = q0 >> 2, c0 = q0 & 3;
                if (shalf == 0 && mtx == cq) {
                    float2* FCn = FC2b + nb*34;
                    FCn[mty]      = (c0 == 0) ? make_float2(e0.x, e0.y)
                                              : make_float2(e0.z, e0.w);
                    FCn[mty + 16] = (c0 == 0) ? make_float2(e1.x, e1.y)
                                              : make_float2(e1.z, e1.w);
                }
            } else if (shalf == 1) {
                const float mv = MV[cur];
                const int a0 = 4*mtx;
                Km[(a0+0)*SP + mty]      = mv*e0.x;
                Km[(a0+1)*SP + mty]      = mv*e0.y;
                Km[(a0+2)*SP + mty]      = mv*e0.z;
                Km[(a0+3)*SP + mty]      = mv*e0.w;
                Km[(a0+0)*SP + mty+16]   = mv*e1.x;
                Km[(a0+1)*SP + mty+16]   = mv*e1.y;
                Km[(a0+2)*SP + mty+16]   = mv*e1.z;
                Km[(a0+3)*SP + mty+16]   = mv*e1.w;
            }
            __syncthreads();
        }

        // ---- P8: Sig = Spr - Km*CSb (w0-3, +Sf); mu_new (w7, +mf) ----
        if (tid < 128) {
            unsigned long long a01,a23,b01,b23;
            mm24(Km, CSb, mty, mtx, a01,a23,b01,b23);
            float4 a0 = pack2(a01,a23);
            float4 a1 = pack2(b01,b23);
            float4 s0 = *(const float4*)(Spr + mty*SP + 4*mtx);
            float4 s1 = *(const float4*)(Spr + (mty+16)*SP + 4*mtx);
            float4 o0 = { s0.x - a0.x, s0.y - a0.y, s0.z - a0.z, s0.w - a0.w };
            float4 o1 = { s1.x - a1.x, s1.y - a1.y, s1.z - a1.z, s1.w - a1.w };
            *(float4*)(Sig + mty*SP + 4*mtx)      = o0;
            *(float4*)(Sig + (mty+16)*SP + 4*mtx) = o1;
            *(float4*)(Sf + bt*1024 + mty*32 + 4*mtx)      = o0;
            *(float4*)(Sf + bt*1024 + (mty+16)*32 + 4*mtx) = o1;
        } else if (tid >= 224) {
            int l = tid - 224;
            float acc = 0.f;
            #pragma unroll
            for (int c = 0; c < 8; ++c) {
                float4 a = *(const float4*)(Km + l*SP + 4*c);
                float4 m = *(const float4*)(rv + 4*c);
                acc += a.x*m.x + a.y*m.y + a.z*m.z + a.w*m.w;
            }
            float mun = mupr[l] + acc;
            mu[l] = mun;
            mf[bt*32 + l] = mun;
        }
        __syncthreads();
    }
}

extern "C" void kernel_launch(void* const* d_in, const int* in_sizes, int n_in,
                              void* d_out, int out_size)
{
    const float* Y    = (const float*)d_in[0];
    const float* U    = (const float*)d_in[1];
    const float* mask = (const float*)d_in[2];
    const float* A    = (const float*)d_in[3];
    const float* Bm   = (const float*)d_in[4];
    const float* C    = (const float*)d_in[5];
    const float* mu0  = (const float*)d_in[6];
    const float* Sig0 = (const float*)d_in[7];
    const float* Q    = (const float*)d_in[8];
    const float* R    = (const float*)d_in[9];

    const int BT = in_sizes[2];
    const int B  = BT / TLEN;

    float* out = (float*)d_out;
    float* mf = out;
    float* Sf = mf + (long long)BT * 32;
    float* mp = Sf + (long long)BT * 1024;
    float* Sp = mp + (long long)BT * 32;

    cudaFuncSetAttribute(kf_kernel, cudaFuncAttributeMaxDynamicSharedMemorySize, SMEM_BYTES);
    kf_kernel<<<B, 256, SMEM_BYTES>>>(Y, U, mask, A, Bm, C, mu0, Sig0, Q, R, mf, Sf, mp, Sp);
}

// round 15
// speedup vs baseline: 1.2752x; 1.0103x over previous
#include <cuda_runtime.h>

#define TLEN 200
#define SP   36
#define BMP  20

// dynamic smem offsets (floats)
#define O_SA   0
#define O_SAT  1152
#define O_SC   2304
#define O_SCT  3456
#define O_SG   4608
#define O_SGT  5760
#define O_SCQ  6912
#define O_SSR  8064
#define O_SIG  9216
#define O_SPR  10368
#define O_CSB  11520
#define O_TM   12672
#define O_KM   13824
#define O_SBM  14976   // 640
#define O_PR   15616   // [2][2][68] = 272
#define O_FC2  15888   // [2][34] float2 = 136 floats
#define O_BB   16024   // [2][4] pivot-block snapshot (B00,B01,B10,B11)
#define O_MU   16032
#define O_MUPR 16064
#define O_RV   16096
#define O_YV   16128   // [2][32]
#define O_UV   16192   // [2][16]
#define O_MV   16224   // [2]
#define SMEM_FLOATS 16232
#define SMEM_BYTES  (SMEM_FLOATS*4)

#define DUP2(d,s)   asm("mov.b64 %0, {%1,%1};" : "=l"(d) : "f"(s))
#define FMA2(d,a,b) asm("fma.rn.f32x2 %0, %1, %2, %0;" : "+l"(d) : "l"(a), "l"(b))
#define MUL2(d,a,b) asm("mul.rn.f32x2 %0, %1, %2;" : "=l"(d) : "l"(a), "l"(b))
#define ADD2(d,a)   asm("add.rn.f32x2 %0, %0, %1;" : "+l"(d) : "l"(a))
#define RCPA(d,a)   asm("rcp.approx.f32 %0, %1;" : "=f"(d) : "f"(a))

__device__ __forceinline__ float2 lo2(unsigned long long u) {
    float2 f;
    f.x = __uint_as_float((unsigned)u);
    f.y = __uint_as_float((unsigned)(u >> 32));
    return f;
}

__device__ __forceinline__ float4 pack2(unsigned long long a, unsigned long long b) {
    float2 u = lo2(a), v = lo2(b);
    float4 o; o.x = u.x; o.y = u.y; o.z = v.x; o.w = v.y;
    return o;
}

// 2x4-tile NN matmul fragment (128 threads, warps 0-3): rows (ty, ty+16) x cols 4tx..
__device__ __forceinline__ void mm24(const float* X, const float* Y,
                                     int ty, int tx,
                                     unsigned long long& a01, unsigned long long& a23,
                                     unsigned long long& b01, unsigned long long& b23)
{
    a01 = a23 = b01 = b23 = 0ULL;
    #pragma unroll
    for (int k4 = 0; k4 < 8; ++k4) {
        float4 x0 = *(const float4*)(X + ty*SP + 4*k4);
        float4 x1 = *(const float4*)(X + (ty+16)*SP + 4*k4);
        #pragma unroll
        for (int kk = 0; kk < 4; ++kk) {
            ulonglong2 y2 = *(const ulonglong2*)(Y + (4*k4+kk)*SP + 4*tx);
            float xs0 = (kk==0)?x0.x:(kk==1)?x0.y:(kk==2)?x0.z:x0.w;
            float xs1 = (kk==0)?x1.x:(kk==1)?x1.y:(kk==2)?x1.z:x1.w;
            unsigned long long xd0, xd1;
            DUP2(xd0, xs0);
            DUP2(xd1, xs1);
            FMA2(a01, xd0, y2.x);
            FMA2(a23, xd0, y2.y);
            FMA2(b01, xd1, y2.x);
            FMA2(b23, xd1, y2.y);
        }
    }
}

// 4x4-tile NN matmul fragment (64 threads): rows 4rg..4rg+3 x cols 4cg..4cg+3.
__device__ __forceinline__ void mm44(const float* X, const float* Y, int rg, int cg,
                                     unsigned long long acc[4][2])
{
    #pragma unroll
    for (int r = 0; r < 4; ++r) { acc[r][0] = 0ULL; acc[r][1] = 0ULL; }
    #pragma unroll
    for (int k4 = 0; k4 < 8; ++k4) {
        float4 x0 = *(const float4*)(X + (4*rg+0)*SP + 4*k4);
        float4 x1 = *(const float4*)(X + (4*rg+1)*SP + 4*k4);
        float4 x2 = *(const float4*)(X + (4*rg+2)*SP + 4*k4);
        float4 x3 = *(const float4*)(X + (4*rg+3)*SP + 4*k4);
        #pragma unroll
        for (int kk = 0; kk < 4; ++kk) {
            ulonglong2 y2 = *(const ulonglong2*)(Y + (4*k4+kk)*SP + 4*cg);
            float s0 = (kk==0)?x0.x:(kk==1)?x0.y:(kk==2)?x0.z:x0.w;
            float s1 = (kk==0)?x1.x:(kk==1)?x1.y:(kk==2)?x1.z:x1.w;
            float s2 = (kk==0)?x2.x:(kk==1)?x2.y:(kk==2)?x2.z:x2.w;
            float s3 = (kk==0)?x3.x:(kk==1)?x3.y:(kk==2)?x3.z:x3.w;
            unsigned long long d0,d1,d2,d3;
            DUP2(d0,s0); DUP2(d1,s1); DUP2(d2,s2); DUP2(d3,s3);
            FMA2(acc[0][0],d0,y2.x); FMA2(acc[0][1],d0,y2.y);
            FMA2(acc[1][0],d1,y2.x); FMA2(acc[1][1],d1,y2.y);
            FMA2(acc[2][0],d2,y2.x); FMA2(acc[2][1],d2,y2.y);
            FMA2(acc[3][0],d3,y2.x); FMA2(acc[3][1],d3,y2.y);
        }
    }
}

__global__ __launch_bounds__(256, 2)
void kf_kernel(const float* __restrict__ Yg, const float* __restrict__ Ug,
               const float* __restrict__ maskg, const float* __restrict__ Ag,
               const float* __restrict__ Bmg, const float* __restrict__ Cg,
               const float* __restrict__ mu0g, const float* __restrict__ Sig0g,
               const float* __restrict__ Qg, const float* __restrict__ Rg,
               float* __restrict__ mf, float* __restrict__ Sf,
               float* __restrict__ mp, float* __restrict__ Sp)
{
    extern __shared__ float dyn[];
    float* sA  = dyn + O_SA;
    float* sAT = dyn + O_SAT;
    float* sC  = dyn + O_SC;
    float* sCT = dyn + O_SCT;
    float* sG  = dyn + O_SG;
    float* sGT = dyn + O_SGT;
    float* sCQ = dyn + O_SCQ;
    float* sSR = dyn + O_SSR;
    float* Sig = dyn + O_SIG;
    float* Spr = dyn + O_SPR;
    float* CSb = dyn + O_CSB;
    float* Tm  = dyn + O_TM;
    float* Km  = dyn + O_KM;
    float* sBm = dyn + O_SBM;
    float* PRb = dyn + O_PR;                 // PR[rb][row01][68]
    float2* FC2b = (float2*)(dyn + O_FC2);   // FC2[rb][34]
    float* BBb = dyn + O_BB;                 // BB[rb][4] = (B00,B01,B10,B11)
    float* mu   = dyn + O_MU;
    float* mupr = dyn + O_MUPR;
    float* rv   = dyn + O_RV;
    float* YV   = dyn + O_YV;
    float* UV   = dyn + O_UV;
    float* MV   = dyn + O_MV;

    const int tid = threadIdx.x;
    const int b   = blockIdx.x;
    const int mty = (tid & 127) >> 3;   // solve/mm24 rows (mty, mty+16)
    const int mtx = tid & 7;            // col group
    const int shalf = tid >> 7;
    const int scol  = mtx + 8*shalf;
    const int idx4  = tid & 63;         // mm44 coords
    const int rg    = idx4 >> 3;
    const int cg    = idx4 & 7;

    const long long btb = (long long)b * TLEN;

    // ---- pre-a: constants, initial state, t=0 inputs ----
    for (int e = tid; e < 1024; e += 256) {
        int i = e >> 5, j = e & 31;
        float a = Ag[e], c = Cg[e];
        sA [i*SP+j] = a;  sAT[j*SP+i] = a;
        sC [i*SP+j] = c;  sCT[j*SP+i] = c;
        Sig[i*SP+j] = Sig0g[e];
        Tm [i*SP+j] = Qg[e];            // Tm temporarily holds Q
    }
    for (int e = tid; e < 512; e += 256) sBm[(e>>4)*BMP + (e&15)] = Bmg[e];
    if (tid < 32) { mu[tid] = mu0g[tid]; YV[tid] = Yg[btb*32 + tid]; }
    else if (tid < 48) UV[tid-32] = Ug[btb*16 + (tid-32)];
    else if (tid == 48) MV[0] = maskg[btb];
    __syncthreads();

    // ---- pre-b: G = C*A (-> sG, sGT), CQ = C*Q (-> sCQ)  [w0-3] ----
    if (tid < 128) {
        unsigned long long a01,a23,b01,b23;
        mm24(sC, sA, mty, mtx, a01,a23,b01,b23);
        *(float4*)(sG + mty*SP + 4*mtx)      = pack2(a01,a23);
        *(float4*)(sG + (mty+16)*SP + 4*mtx) = pack2(b01,b23);
        float2 A01=lo2(a01),A23=lo2(a23),B01f=lo2(b01),B23f=lo2(b23);
        sGT[(4*mtx+0)*SP + mty] = A01.x;  sGT[(4*mtx+1)*SP + mty] = A01.y;
        sGT[(4*mtx+2)*SP + mty] = A23.x;  sGT[(4*mtx+3)*SP + mty] = A23.y;
        sGT[(4*mtx+0)*SP + mty+16] = B01f.x;  sGT[(4*mtx+1)*SP + mty+16] = B01f.y;
        sGT[(4*mtx+2)*SP + mty+16] = B23f.x;  sGT[(4*mtx+3)*SP + mty+16] = B23f.y;
        mm24(sC, Tm, mty, mtx, a01,a23,b01,b23);
        *(float4*)(sCQ + mty*SP + 4*mtx)      = pack2(a01,a23);
        *(float4*)(sCQ + (mty+16)*SP + 4*mtx) = pack2(b01,b23);
    }
    __syncthreads();

    // ---- pre-c: SR0 = CQ*C^T + R -> sSR  [w0-3] ----
    if (tid < 128) {
        unsigned long long a01,a23,b01,b23;
        mm24(sCQ, sCT, mty, mtx, a01,a23,b01,b23);
        ulonglong2 r0 = __ldg((const ulonglong2*)(Rg + mty*32 + 4*mtx));
        ulonglong2 r1 = __ldg((const ulonglong2*)(Rg + (mty+16)*32 + 4*mtx));
        ADD2(a01, r0.x); ADD2(a23, r0.y); ADD2(b01, r1.x); ADD2(b23, r1.y);
        *(float4*)(sSR + mty*SP + 4*mtx)      = pack2(a01,a23);
        *(float4*)(sSR + (mty+16)*SP + 4*mtx) = pack2(b01,b23);
    }
    __syncthreads();

    // hoisted per-thread constants
    ulonglong2 sru0 = make_ulonglong2(0,0), sru1 = make_ulonglong2(0,0);
    if (tid < 128) {
        sru0 = *(const ulonglong2*)(sSR + mty*SP + 4*mtx);
        sru1 = *(const ulonglong2*)(sSR + (mty+16)*SP + 4*mtx);
    }
    ulonglong2 qh[4];
    if (tid < 64) {
        #pragma unroll
        for (int r = 0; r < 4; ++r)
            qh[r] = __ldg((const ulonglong2*)(Qg + (4*rg+r)*32 + 4*cg));
    }

    for (int t = 0; t < TLEN; ++t) {
        const long long bt = btb + t;
        const int cur = t & 1, nxtb = cur ^ 1;

        // ---- P1: T1 = A*Sig (w0-1) || T2 = G*Sig (w2-3) || stage t+1 (w4-5) ----
        if (tid < 64) {
            unsigned long long acc[4][2];
            mm44(sA, Sig, rg, cg, acc);
            #pragma unroll
            for (int r = 0; r < 4; ++r)
                *(float4*)(Tm + (4*rg+r)*SP + 4*cg) = pack2(acc[r][0], acc[r][1]);
        } else if (tid < 128) {
            unsigned long long acc[4][2];
            mm44(sG, Sig, rg, cg, acc);
            #pragma unroll
            for (int r = 0; r < 4; ++r)
                *(float4*)(Km + (4*rg+r)*SP + 4*cg) = pack2(acc[r][0], acc[r][1]);
        } else if (t + 1 < TLEN) {
            if (tid < 160)       YV[nxtb*32 + (tid-128)] = Yg[(bt+1)*32 + (tid-128)];
            else if (tid < 176)  UV[nxtb*16 + (tid-160)] = Ug[(bt+1)*16 + (tid-160)];
            else if (tid == 176) MV[nxtb] = maskg[bt+1];
        }
        __syncthreads();

        // ---- P2: Spr = T1*A^T + Q (w0-1) || CSb = T2*A^T + CQ (w2-3) || mu_pred (w7) ----
        if (tid < 64) {
            unsigned long long acc[4][2];
            mm44(Tm, sAT, rg, cg, acc);
            #pragma unroll
            for (int r = 0; r < 4; ++r) {
                ADD2(acc[r][0], qh[r].x);
                ADD2(acc[r][1], qh[r].y);
                *(float4*)(Spr + (4*rg+r)*SP + 4*cg) = pack2(acc[r][0], acc[r][1]);
            }
        } else if (tid < 128) {
            unsigned long long acc[4][2];
            mm44(Km, sAT, rg, cg, acc);
            #pragma unroll
            for (int r = 0; r < 4; ++r) {
                ulonglong2 cq = *(const ulonglong2*)(sCQ + (4*rg+r)*SP + 4*cg);
                ADD2(acc[r][0], cq.x);
                ADD2(acc[r][1], cq.y);
                *(float4*)(CSb + (4*rg+r)*SP + 4*cg) = pack2(acc[r][0], acc[r][1]);
            }
        } else if (tid >= 224) {
            int l = tid - 224;
            float acc = 0.f;
            #pragma unroll
            for (int c = 0; c < 8; ++c) {
                float4 a = *(const float4*)(sA + l*SP + 4*c);
                float4 m = *(const float4*)(mu + 4*c);
                acc += a.x*m.x + a.y*m.y + a.z*m.z + a.w*m.w;
            }
            #pragma unroll
            for (int c = 0; c < 4; ++c) {
                float4 a = *(const float4*)(sBm + l*BMP + 4*c);
                float4 m = *(const float4*)(UV + cur*16 + 4*c);
                acc += a.x*m.x + a.y*m.y + a.z*m.z + a.w*m.w;
            }
            mupr[l] = acc;
            mp[bt*32 + l] = acc;
        }
        __syncthreads();

        // ---- P3/seed: S = T2*G^T + SR0 fused into solve regs (w0-3);
        //               CS slices (w4-7); Sp store (w4-6); rv (w7) ----
        unsigned long long e0a, e0b, e1a, e1b;   // rows (mty, mty+16), cols 4scol..
        if (shalf == 0) {
            mm24(Km, sGT, mty, mtx, e0a, e0b, e1a, e1b);   // Km holds T2
            ADD2(e0a, sru0.x); ADD2(e0b, sru0.y);
            ADD2(e1a, sru1.x); ADD2(e1b, sru1.y);
        } else {
            ulonglong2 c0 = *(const ulonglong2*)(CSb + mty*SP + 4*mtx);
            ulonglong2 c1 = *(const ulonglong2*)(CSb + (mty+16)*SP + 4*mtx);
            e0a = c0.x; e0b = c0.y; e1a = c1.x; e1b = c1.y;
            if (tid < 224) {
                for (int f = tid - 128; f < 256; f += 96) {
                    int row = f >> 3, c4 = f & 7;
                    float4 v = *(const float4*)(Spr + row*SP + 4*c4);
                    *(float4*)(Sp + bt*1024 + f*4) = v;
                }
            } else {
                int l = tid - 224;
                float acc = YV[cur*32 + l];
                #pragma unroll
                for (int c = 0; c < 8; ++c) {
                    float4 a = *(const float4*)(sC + l*SP + 4*c);
                    float4 m = *(const float4*)(mupr + 4*c);
                    acc -= a.x*m.x + a.y*m.y + a.z*m.z + a.w*m.w;
                }
                rv[l] = acc;
            }
        }
        // seed snapshots for pivot pair (0,1)
        if (mty == 0) *(ulonglong2*)(PRb + 0*68 + 4*scol) = make_ulonglong2(e0a, e0b);
        if (mty == 1) *(ulonglong2*)(PRb + 1*68 + 4*scol) = make_ulonglong2(e0a, e0b);
        if (shalf == 0 && mtx == 0) {
            FC2b[mty]      = lo2(e0a);
            FC2b[mty + 16] = lo2(e1a);
            if (mty == 0) *(float2*)(BBb + 0) = lo2(e0a);   // (B00,B01)
            if (mty == 1) *(float2*)(BBb + 2) = lo2(e0a);   // (B10,B11)
        }
        __syncthreads();

        // ---- 16 paired-pivot Gauss-Jordan rounds, f32x2-packed ----
        #pragma unroll
        for (int rr = 0; rr < 16; ++rr) {
            const int rb = rr & 1, nb = rb ^ 1;
            const int p0 = 2*rr, p1 = 2*rr + 1;
            const float* PR0 = PRb + (rb*2)*68;
            const float* PR1 = PR0 + 68;
            const float2* FCc = FC2b + rb*34;
            float4 bb = *(const float4*)(BBb + rb*4);       // (B00,B01,B10,B11)
            ulonglong2 P0 = *(const ulonglong2*)(PR0 + 4*scol);
            ulonglong2 P1 = *(const ulonglong2*)(PR1 + 4*scol);
            float det = bb.x*bb.w - bb.y*bb.z;
            float dinv;
            RCPA(dinv, det);
            float i00 =  bb.w*dinv, i01 = -bb.y*dinv;
            float i10 = -bb.z*dinv, i11 =  bb.x*dinv;
            unsigned long long di00, di01, di10, di11;
            DUP2(di00, i00); DUP2(di01, i01); DUP2(di10, i10); DUP2(di11, i11);
            unsigned long long W0a, W0b, W1a, W1b;
            MUL2(W0a, di00, P0.x); FMA2(W0a, di01, P1.x);
            MUL2(W0b, di00, P0.y); FMA2(W0b, di01, P1.y);
            MUL2(W1a, di10, P0.x); FMA2(W1a, di11, P1.x);
            MUL2(W1b, di10, P0.y); FMA2(W1b, di11, P1.y);
            float2 f0 = FCc[mty];
            float2 f1 = FCc[mty + 16];
            float ng00 = ((mty      == p0) ? 1.f : 0.f) - f0.x;   // delta - g
            float ng01 = ((mty      == p1) ? 1.f : 0.f) - f0.y;
            float ng10 = ((mty + 16 == p0) ? 1.f : 0.f) - f1.x;
            float ng11 = ((mty + 16 == p1) ? 1.f : 0.f) - f1.y;
            unsigned long long dn00, dn01, dn10, dn11;
            DUP2(dn00, ng00); DUP2(dn01, ng01); DUP2(dn10, ng10); DUP2(dn11, ng11);
            // e += ng * W   (== e - (g-delta)*W)
            FMA2(e0a, dn00, W0a); FMA2(e0a, dn01, W1a);
            FMA2(e0b, dn00, W0b); FMA2(e0b, dn01, W1b);
            FMA2(e1a, dn10, W0a); FMA2(e1a, dn11, W1a);
            FMA2(e1b, dn10, W0b); FMA2(e1b, dn11, W1b);
            if (rr < 15) {
                const int q0 = p0 + 2, q1 = p0 + 3;
                float* PN0 = PRb + (nb*2)*68;
                float* PN1 = PN0 + 68;
                if (mty      == q0) *(ulonglong2*)(PN0 + 4*scol) = make_ulonglong2(e0a, e0b);
                if (mty + 16 == q0) *(ulonglong2*)(PN0 + 4*scol) = make_ulonglong2(e1a, e1b);
                if (mty      == q1) *(ulonglong2*)(PN1 + 4*scol) = make_ulonglong2(e0a, e0b);
                if (mty + 16 == q1) *(ulonglong2*)(PN1 + 4*scol) = make_ulonglong2(e1a, e1b);
                const int cq = q0 >> 2, c0 = q0 & 3;   // c0 in {0,2}
                if (shalf == 0 && mtx == cq) {
                    float2* FCn = FC2b + nb*34;
                    float2 v0 = (c0 == 0) ? lo2(e0a) : lo2(e0b);
                    float2 v1 = (c0 == 0) ? lo2(e1a) : lo2(e1b);
                    FCn[mty]      = v0;
                    FCn[mty + 16] = v1;
                    // pivot-block snapshot for next round
                    if (mty      == q0) *(float2*)(BBb + nb*4 + 0) = v0;
                    if (mty + 16 == q0) *(float2*)(BBb + nb*4 + 0) = v1;
                    if (mty      == q1) *(float2*)(BBb + nb*4 + 2) = v0;
                    if (mty + 16 == q1) *(float2*)(BBb + nb*4 + 2) = v1;
                }
            } else if (shalf == 1) {
                // K = mval * X^T into Km
                const float mv = MV[cur];
                const int a0 = 4*mtx;
                float2 u0 = lo2(e0a), u1 = lo2(e0b), v0 = lo2(e1a), v1 = lo2(e1b);
                Km[(a0+0)*SP + mty]      = mv*u0.x;
                Km[(a0+1)*SP + mty]      = mv*u0.y;
                Km[(a0+2)*SP + mty]      = mv*u1.x;
                Km[(a0+3)*SP + mty]      = mv*u1.y;
                Km[(a0+0)*SP + mty+16]   = mv*v0.x;
                Km[(a0+1)*SP + mty+16]   = mv*v0.y;
                Km[(a0+2)*SP + mty+16]   = mv*v1.x;
                Km[(a0+3)*SP + mty+16]   = mv*v1.y;
            }
            __syncthreads();
        }

        // ---- P8: Sig = Spr - Km*CSb (w0-3, +Sf); mu_new (w7, +mf) ----
        if (tid < 128) {
            unsigned long long a01,a23,b01,b23;
            mm24(Km, CSb, mty, mtx, a01,a23,b01,b23);
            float4 a0 = pack2(a01,a23);
            float4 a1 = pack2(b01,b23);
            float4 s0 = *(const float4*)(Spr + mty*SP + 4*mtx);
            float4 s1 = *(const float4*)(Spr + (mty+16)*SP + 4*mtx);
            float4 o0 = { s0.x - a0.x, s0.y - a0.y, s0.z - a0.z, s0.w - a0.w };
            float4 o1 = { s1.x - a1.x, s1.y - a1.y, s1.z - a1.z, s1.w - a1.w };
            *(float4*)(Sig + mty*SP + 4*mtx)      = o0;
            *(float4*)(Sig + (mty+16)*SP + 4*mtx) = o1;
            *(float4*)(Sf + bt*1024 + mty*32 + 4*mtx)      = o0;
            *(float4*)(Sf + bt*1024 + (mty+16)*32 + 4*mtx) = o1;
        } else if (tid >= 224) {
            int l = tid - 224;
            float acc = 0.f;
            #pragma unroll
            for (int c = 0; c < 8; ++c) {
                float4 a = *(const float4*)(Km + l*SP + 4*c);
                float4 m = *(const float4*)(rv + 4*c);
                acc += a.x*m.x + a.y*m.y + a.z*m.z + a.w*m.w;
            }
            float mun = mupr[l] + acc;
            mu[l] = mun;
            mf[bt*32 + l] = mun;
        }
        __syncthreads();
    }
}

extern "C" void kernel_launch(void* const* d_in, const int* in_sizes, int n_in,
                              void* d_out, int out_size)
{
    const float* Y    = (const float*)d_in[0];
    const float* U    = (const float*)d_in[1];
    const float* mask = (const float*)d_in[2];
    const float* A    = (const float*)d_in[3];
    const float* Bm   = (const float*)d_in[4];
    const float* C    = (const float*)d_in[5];
    const float* mu0  = (const float*)d_in[6];
    const float* Sig0 = (const float*)d_in[7];
    const float* Q    = (const float*)d_in[8];
    const float* R    = (const float*)d_in[9];

    const int BT = in_sizes[2];
    const int B  = BT / TLEN;

    float* out = (float*)d_out;
    float* mf = out;
    float* Sf = mf + (long long)BT * 32;
    float* mp = Sf + (long long)BT * 1024;
    float* Sp = mp + (long long)BT * 32;

    cudaFuncSetAttribute(kf_kernel, cudaFuncAttributeMaxDynamicSharedMemorySize, SMEM_BYTES);
    kf_kernel<<<B, 256, SMEM_BYTES>>>(Y, U, mask, A, Bm, C, mu0, Sig0, Q, R, mf, Sf, mp, Sp);
}